// round 2
// baseline (speedup 1.0000x reference)
#include <cuda_runtime.h>
#include <math.h>

#define N_ENT  100000
#define N_REL  500
#define N_TRIP 250000
#define D      128
#define D3     384
#define M_ROWS 500000.0f
#define BN_EPS 1e-5f
#define SLOPE  0.01f
#define NREP   32

// ---------------- device scratch (static: no allocation allowed) -------------
__device__ float g_E[(size_t)N_ENT * 256];       // [e][0:128]=E0w, [128:256]=E1w
__device__ float g_R[N_REL * D];                 // Rw
__device__ float g_Wcat[D * 256];                // [j][k], k<128 -> W0', k>=128 -> W1'
__device__ float g_Wr[D * D];                    // [j][k]
__device__ float g_biasp[D];
__device__ float g_s0[D3], g_t0[D3];
__device__ float g_sum0[D], g_sumsq0[D], g_sumsqr[D];
__device__ float g_sum1[D], g_sumsq1[D];
__device__ float g_s1[D], g_t1c[D], g_w2[D];
__device__ float g_c2;
__device__ int   g_entcnt[N_ENT];
__device__ int   g_relcnt[N_REL];
__device__ float g_ebs[N_ENT];
__device__ float g_relbuf[(size_t)NREP * N_REL * D];

// vectorized reduction: one instruction per 16B (PTX ISA 8.1+, sm_90+)
__device__ __forceinline__ void red_add_v4(float* addr, float x, float y, float z, float w) {
    asm volatile("red.global.add.v4.f32 [%0], {%1,%2,%3,%4};"
                 :: "l"(addr), "f"(x), "f"(y), "f"(z), "f"(w) : "memory");
}

// ---------------- zeroing ----------------------------------------------------
__global__ void zero_out_k(float* __restrict__ p, int n) {
    int stride = gridDim.x * blockDim.x;
    for (int i = blockIdx.x * blockDim.x + threadIdx.x; i < n; i += stride) p[i] = 0.f;
}
__global__ void zero_misc_k() {
    int i = blockIdx.x * blockDim.x + threadIdx.x;
    if (i < N_ENT) { g_entcnt[i] = 0; g_ebs[i] = 0.f; }
    if (i < N_REL) g_relcnt[i] = 0;
    if (i < D) {
        g_sum0[i] = 0.f; g_sumsq0[i] = 0.f; g_sumsqr[i] = 0.f;
        g_sum1[i] = 0.f; g_sumsq1[i] = 0.f;
    }
}
__global__ void zero_relbuf_k() {
    int n = NREP * N_REL * D;
    int stride = gridDim.x * blockDim.x;
    for (int i = blockIdx.x * blockDim.x + threadIdx.x; i < n; i += stride) g_relbuf[i] = 0.f;
}

// ---------------- histogram --------------------------------------------------
__global__ void count_k(const int* __restrict__ trip) {
    int i = blockIdx.x * blockDim.x + threadIdx.x;
    if (i < N_TRIP) {
        atomicAdd(&g_entcnt[trip[3 * i]], 1);
        atomicAdd(&g_entcnt[trip[3 * i + 1]], 1);
        atomicAdd(&g_relcnt[trip[3 * i + 2]], 1);
    }
}

// ---------------- BN0 stats (count-weighted moments) -------------------------
__global__ void bn0_ent_stats_k(const float* __restrict__ ent) {
    int j = threadIdx.x & 127;
    int half = threadIdx.x >> 7;
    float s = 0.f, ss = 0.f;
    for (int e = blockIdx.x * 2 + half; e < N_ENT; e += gridDim.x * 2) {
        float w = (float)g_entcnt[e];
        float v = ent[(size_t)e * D + j];
        s  += w * v;
        ss += w * v * v;
    }
    atomicAdd(&g_sum0[j], s);
    atomicAdd(&g_sumsq0[j], ss);
}
__global__ void bn0_rel_stats_k(const float* __restrict__ rel) {
    int j = threadIdx.x;
    float ss = 0.f;
    for (int r = 0; r < N_REL; r++) {
        float w = (float)g_relcnt[r];
        float v = rel[r * D + j];
        ss += w * v * v;
    }
    g_sumsqr[j] = ss;
}
__global__ void bn0_fin_k(const float* __restrict__ g0, const float* __restrict__ b0) {
    int j = threadIdx.x;  // 0..383
    float mean, var;
    if (j < 256) {
        int jj = j & 127;
        mean = g_sum0[jj] * (1.f / M_ROWS);
        var  = g_sumsq0[jj] * (1.f / M_ROWS) - mean * mean;
    } else {
        int jj = j - 256;
        mean = 0.f;
        var  = 2.f * g_sumsqr[jj] * (1.f / M_ROWS);
    }
    float inv = rsqrtf(var + BN_EPS);
    float s = inv * g0[j];
    g_s0[j] = s;
    g_t0[j] = b0[j] - mean * s;
}

// ---------------- fold BN0 into weights --------------------------------------
__global__ void wprep_k(const float* __restrict__ aw, const float* __restrict__ ab) {
    int k = blockIdx.x;   // output col 0..127
    int j = threadIdx.x;  // 0..383
    float w  = aw[k * D3 + j];
    float sc = w * g_s0[j];
    if (j < D)          g_Wcat[j * 256 + k] = sc;
    else if (j < 256)   g_Wcat[(j - D) * 256 + D + k] = sc;
    else                g_Wr[(j - 256) * D + k] = sc;
    __shared__ float red[D3];
    red[j] = g_t0[j] * w;
    __syncthreads();
    if (j < D) red[j] += red[j + D] + red[j + 256];
    __syncthreads();
    for (int off = 64; off > 0; off >>= 1) {
        if (j < off) red[j] += red[j + off];
        __syncthreads();
    }
    if (j == 0) g_biasp[k] = ab[k] + red[0];
}

// ---------------- E = ent_embed @ Wcat  (100000 x 256, K=128) ---------------
__global__ void gemm_k(const float* __restrict__ A) {
    __shared__ float As[16][128];
    __shared__ float Bs[16][128];
    int bm = blockIdx.x * 128, bn = blockIdx.y * 128;
    int tx = threadIdx.x & 15, ty = threadIdx.x >> 4;
    float acc[8][8];
#pragma unroll
    for (int i = 0; i < 8; i++)
#pragma unroll
        for (int jj = 0; jj < 8; jj++) acc[i][jj] = 0.f;

    for (int k0 = 0; k0 < D; k0 += 16) {
        for (int t = threadIdx.x; t < 128 * 16; t += 256) {
            int m = t >> 4, k = t & 15;
            int row = bm + m;
            As[k][m] = (row < N_ENT) ? A[(size_t)row * D + k0 + k] : 0.f;
        }
        for (int t = threadIdx.x; t < 16 * 128; t += 256) {
            int k = t >> 7, n = t & 127;
            Bs[k][n] = g_Wcat[(k0 + k) * 256 + bn + n];
        }
        __syncthreads();
#pragma unroll
        for (int k = 0; k < 16; k++) {
            float4 a0 = *(const float4*)&As[k][ty * 8];
            float4 a1 = *(const float4*)&As[k][ty * 8 + 4];
            float4 b0 = *(const float4*)&Bs[k][tx * 8];
            float4 b1 = *(const float4*)&Bs[k][tx * 8 + 4];
            float av[8] = {a0.x, a0.y, a0.z, a0.w, a1.x, a1.y, a1.z, a1.w};
            float bv[8] = {b0.x, b0.y, b0.z, b0.w, b1.x, b1.y, b1.z, b1.w};
#pragma unroll
            for (int i = 0; i < 8; i++)
#pragma unroll
                for (int jj = 0; jj < 8; jj++) acc[i][jj] += av[i] * bv[jj];
        }
        __syncthreads();
    }
#pragma unroll
    for (int i = 0; i < 8; i++) {
        int row = bm + ty * 8 + i;
        if (row < N_ENT) {
            float* dst = &g_E[(size_t)row * 256 + bn + tx * 8];
            *(float4*)dst       = make_float4(acc[i][0], acc[i][1], acc[i][2], acc[i][3]);
            *(float4*)(dst + 4) = make_float4(acc[i][4], acc[i][5], acc[i][6], acc[i][7]);
        }
    }
}

// ---------------- R = rel_embed @ Wr  (500 x 128) ---------------------------
__global__ void relgemm_k(const float* __restrict__ rel) {
    int r = blockIdx.x, k = threadIdx.x;
    __shared__ float rr[D];
    rr[k] = rel[r * D + k];
    __syncthreads();
    float acc = 0.f;
#pragma unroll 8
    for (int j = 0; j < D; j++) acc += rr[j] * g_Wr[j * D + k];
    g_R[r * D + k] = acc;
}

// ---------------- pass 1: BN1 column moments over 500k virtual rows ---------
__global__ void pass1_k(const int* __restrict__ trip) {
    int lane = threadIdx.x & 31;
    int warp = (blockIdx.x * blockDim.x + threadIdx.x) >> 5;
    int nw = (gridDim.x * blockDim.x) >> 5;
    float4 bias = ((const float4*)g_biasp)[lane];
    float sx = 0.f, sy = 0.f, sz = 0.f, sw = 0.f;
    float qx = 0.f, qy = 0.f, qz = 0.f, qw = 0.f;
    for (int i = warp; i < N_TRIP; i += nw) {
        int t0 = trip[3 * i], t1 = trip[3 * i + 1], t2 = trip[3 * i + 2];
        const float4* p0 = (const float4*)(g_E + (size_t)t0 * 256);
        const float4* p1 = (const float4*)(g_E + (size_t)t1 * 256);
        float4 a = p0[lane], dd = p0[lane + 32];
        float4 c = p1[lane], b  = p1[lane + 32];
        float4 r = ((const float4*)(g_R + (size_t)t2 * D))[lane];
        float cfx = a.x + b.x + r.x + bias.x, cbx = c.x + dd.x - r.x + bias.x;
        float cfy = a.y + b.y + r.y + bias.y, cby = c.y + dd.y - r.y + bias.y;
        float cfz = a.z + b.z + r.z + bias.z, cbz = c.z + dd.z - r.z + bias.z;
        float cfw = a.w + b.w + r.w + bias.w, cbw = c.w + dd.w - r.w + bias.w;
        sx += cfx + cbx; qx += cfx * cfx + cbx * cbx;
        sy += cfy + cby; qy += cfy * cfy + cby * cby;
        sz += cfz + cbz; qz += cfz * cfz + cbz * cbz;
        sw += cfw + cbw; qw += cfw * cfw + cbw * cbw;
    }
    red_add_v4(&g_sum1[lane * 4], sx, sy, sz, sw);
    red_add_v4(&g_sumsq1[lane * 4], qx, qy, qz, qw);
}

__global__ void bn1_fin_k(const float* __restrict__ g1, const float* __restrict__ b1,
                          const float* __restrict__ a2w, const float* __restrict__ a2b) {
    int k = threadIdx.x;  // 0..127
    float mean = g_sum1[k] * (1.f / M_ROWS);
    float var  = g_sumsq1[k] * (1.f / M_ROWS) - mean * mean;
    float inv  = rsqrtf(var + BN_EPS);
    float s = inv * g1[k];
    float t = b1[k] - mean * s;
    g_s1[k] = s;
    g_t1c[k] = t;
    // pass2 materializes the FULL post-BN1 c, so the attention dot uses the
    // raw a2 weights: d = c . a2w + a2b.  (Round-1 bug: had a2w*s1 here plus
    // a t1-folded constant -> double-applied BN1.)
    g_w2[k] = a2w[k];
    if (k == 0) g_c2 = a2b[0];
}

// ---------------- pass 2: attention + scatter --------------------------------
__global__ void pass2_k(const int* __restrict__ trip, float* __restrict__ hs) {
    int lane = threadIdx.x & 31;
    int warp = (blockIdx.x * blockDim.x + threadIdx.x) >> 5;
    int nw = (gridDim.x * blockDim.x) >> 5;
    int rep = blockIdx.x & (NREP - 1);
    float4 bias = ((const float4*)g_biasp)[lane];
    float4 s1v  = ((const float4*)g_s1)[lane];
    float4 t1v  = ((const float4*)g_t1c)[lane];
    float4 w2v  = ((const float4*)g_w2)[lane];
    float c2 = g_c2;
    for (int i = warp; i < N_TRIP; i += nw) {
        int t0 = trip[3 * i], t1i = trip[3 * i + 1], t2 = trip[3 * i + 2];
        const float4* p0 = (const float4*)(g_E + (size_t)t0 * 256);
        const float4* p1 = (const float4*)(g_E + (size_t)t1i * 256);
        float4 a = p0[lane], dd = p0[lane + 32];
        float4 c = p1[lane], b  = p1[lane + 32];
        float4 r = ((const float4*)(g_R + (size_t)t2 * D))[lane];
        float cfx = (a.x + b.x + r.x + bias.x) * s1v.x + t1v.x;
        float cfy = (a.y + b.y + r.y + bias.y) * s1v.y + t1v.y;
        float cfz = (a.z + b.z + r.z + bias.z) * s1v.z + t1v.z;
        float cfw = (a.w + b.w + r.w + bias.w) * s1v.w + t1v.w;
        float cbx = (c.x + dd.x - r.x + bias.x) * s1v.x + t1v.x;
        float cby = (c.y + dd.y - r.y + bias.y) * s1v.y + t1v.y;
        float cbz = (c.z + dd.z - r.z + bias.z) * s1v.z + t1v.z;
        float cbw = (c.w + dd.w - r.w + bias.w) * s1v.w + t1v.w;
        float df = cfx * w2v.x + cfy * w2v.y + cfz * w2v.z + cfw * w2v.w;
        float db = cbx * w2v.x + cby * w2v.y + cbz * w2v.z + cbw * w2v.w;
#pragma unroll
        for (int off = 16; off > 0; off >>= 1) {
            df += __shfl_xor_sync(0xFFFFFFFFu, df, off);
            db += __shfl_xor_sync(0xFFFFFFFFu, db, off);
        }
        df += c2; db += c2;
        float bf = (df >= 0.f) ? -df : -SLOPE * df;
        float bb = (db >= 0.f) ? -db : -SLOPE * db;
        float ef = expf(bf);
        float eb = expf(bb);
        red_add_v4(hs + (size_t)t0 * D + lane * 4, cfx * ef, cfy * ef, cfz * ef, cfw * ef);
        red_add_v4(hs + (size_t)t1i * D + lane * 4, cbx * eb, cby * eb, cbz * eb, cbw * eb);
        red_add_v4(g_relbuf + ((size_t)rep * N_REL + t2) * D + lane * 4,
                   cfx * ef, cfy * ef, cfz * ef, cfw * ef);
        if (lane == 0) {
            atomicAdd(&g_ebs[t0], ef);
            atomicAdd(&g_ebs[t1i], eb);
        }
    }
}

// ---------------- finalize ----------------------------------------------------
__global__ void ent_final_k(float* __restrict__ out) {
    int i = blockIdx.x * blockDim.x + threadIdx.x;
    if (i < N_ENT * D) {
        float denom = g_ebs[i >> 7];
        if (denom == 0.f) denom = 1e-12f;
        out[i] = out[i] / denom;
    }
}
__global__ void rel_final_k(float* __restrict__ out) {
    int i = blockIdx.x * blockDim.x + threadIdx.x;
    if (i < N_REL * D) {
        float s = 0.f;
#pragma unroll
        for (int rp = 0; rp < NREP; rp++) s += g_relbuf[(size_t)rp * N_REL * D + i];
        float cnt = (float)g_relcnt[i >> 7];
        out[(size_t)N_ENT * D + i] = s / fmaxf(cnt, 1.f);
    }
}

// ---------------- launch ------------------------------------------------------
extern "C" void kernel_launch(void* const* d_in, const int* in_sizes, int n_in,
                              void* d_out, int out_size) {
    const int*   trip = (const int*)d_in[0];
    const float* ent  = (const float*)d_in[1];
    const float* rel  = (const float*)d_in[2];
    const float* aw   = (const float*)d_in[3];
    const float* ab   = (const float*)d_in[4];
    const float* a2w  = (const float*)d_in[5];
    const float* a2b  = (const float*)d_in[6];
    const float* bn0g = (const float*)d_in[7];
    const float* bn0b = (const float*)d_in[8];
    const float* bn1g = (const float*)d_in[9];
    const float* bn1b = (const float*)d_in[10];
    float* out = (float*)d_out;

    zero_out_k<<<8192, 256>>>(out, N_ENT * D + N_REL * D);
    zero_misc_k<<<(N_ENT + 255) / 256, 256>>>();
    zero_relbuf_k<<<8192, 256>>>();
    count_k<<<(N_TRIP + 255) / 256, 256>>>(trip);
    bn0_ent_stats_k<<<592, 256>>>(ent);
    bn0_rel_stats_k<<<1, 128>>>(rel);
    bn0_fin_k<<<1, 384>>>(bn0g, bn0b);
    wprep_k<<<128, 384>>>(aw, ab);
    gemm_k<<<dim3(782, 2), 256>>>(ent);
    relgemm_k<<<N_REL, 128>>>(rel);
    pass1_k<<<1184, 256>>>(trip);
    bn1_fin_k<<<1, 128>>>(bn1g, bn1b, a2w, a2b);
    pass2_k<<<1184, 256>>>(trip, out);
    ent_final_k<<<(N_ENT * D + 255) / 256, 256>>>(out);
    rel_final_k<<<(N_REL * D + 255) / 256, 256>>>(out);
}

// round 3
// speedup vs baseline: 1.4634x; 1.4634x over previous
#include <cuda_runtime.h>
#include <math.h>
#include <stdint.h>

#define N_ENT  100000
#define N_REL  500
#define N_TRIP 250000
#define D      128
#define D3     384
#define M_ROWS 500000.0f
#define BN_EPS 1e-5f
#define SLOPE  0.01f
#define NREP   32

// ---------------- device scratch (static: no allocation allowed) -------------
__device__ float g_E[(size_t)N_ENT * 256];       // [e][0:128]=E0w, [128:256]=E1w
__device__ float g_R[N_REL * D];                 // Rw
__device__ float g_Wcat[D * 256];                // [j][k], k<128 -> W0', k>=128 -> W1'
__device__ float g_Wr[D * D];                    // [j][k]
__device__ float g_biasp[D];
__device__ float g_s0[D3], g_t0[D3];
__device__ float g_sum0[D], g_sumsq0[D], g_sumsqr[D];
__device__ float g_sum1[D], g_sumsq1[D];
__device__ float g_s1[D], g_t1c[D], g_w2[D];
__device__ float g_c2;
__device__ int   g_entcnt[N_ENT];
__device__ int   g_relcnt[N_REL];
__device__ float g_ebs[N_ENT];
__device__ float g_relbuf[(size_t)NREP * N_REL * D];

// vectorized reduction: one instruction per 16B (PTX ISA 8.1+, sm_90+)
__device__ __forceinline__ void red_add_v4(float* addr, float x, float y, float z, float w) {
    asm volatile("red.global.add.v4.f32 [%0], {%1,%2,%3,%4};"
                 :: "l"(addr), "f"(x), "f"(y), "f"(z), "f"(w) : "memory");
}

__device__ __forceinline__ uint32_t f2tf(float x) {
    uint32_t u;
    asm("cvt.rna.tf32.f32 %0, %1;" : "=r"(u) : "f"(x));
    return u;
}

__device__ __forceinline__ void mma_tf32(float* d, const uint32_t* a, const uint32_t* b) {
    asm volatile(
        "mma.sync.aligned.m16n8k8.row.col.f32.tf32.tf32.f32 "
        "{%0,%1,%2,%3}, {%4,%5,%6,%7}, {%8,%9}, {%0,%1,%2,%3};"
        : "+f"(d[0]), "+f"(d[1]), "+f"(d[2]), "+f"(d[3])
        : "r"(a[0]), "r"(a[1]), "r"(a[2]), "r"(a[3]), "r"(b[0]), "r"(b[1]));
}

// ---------------- zeroing ----------------------------------------------------
__global__ void zero_out_k(float4* __restrict__ p, int n4) {
    int stride = gridDim.x * blockDim.x;
    float4 z = make_float4(0.f, 0.f, 0.f, 0.f);
    for (int i = blockIdx.x * blockDim.x + threadIdx.x; i < n4; i += stride) p[i] = z;
}
__global__ void zero_misc_k() {
    int i = blockIdx.x * blockDim.x + threadIdx.x;
    if (i < N_ENT) { g_entcnt[i] = 0; g_ebs[i] = 0.f; }
    if (i < N_REL) g_relcnt[i] = 0;
    if (i < D) {
        g_sum0[i] = 0.f; g_sumsq0[i] = 0.f; g_sumsqr[i] = 0.f;
        g_sum1[i] = 0.f; g_sumsq1[i] = 0.f;
    }
}
__global__ void zero_relbuf_k() {
    int n4 = NREP * N_REL * D / 4;
    float4* p = (float4*)g_relbuf;
    float4 z = make_float4(0.f, 0.f, 0.f, 0.f);
    int stride = gridDim.x * blockDim.x;
    for (int i = blockIdx.x * blockDim.x + threadIdx.x; i < n4; i += stride) p[i] = z;
}

// ---------------- histogram (smem aggregation kills rel-atomic contention) ---
__global__ void count_k(const int* __restrict__ trip) {
    __shared__ int relh[N_REL];
    for (int j = threadIdx.x; j < N_REL; j += blockDim.x) relh[j] = 0;
    __syncthreads();
    int stride = gridDim.x * blockDim.x;
    for (int i = blockIdx.x * blockDim.x + threadIdx.x; i < N_TRIP; i += stride) {
        atomicAdd(&g_entcnt[trip[3 * i]], 1);
        atomicAdd(&g_entcnt[trip[3 * i + 1]], 1);
        atomicAdd(&relh[trip[3 * i + 2]], 1);
    }
    __syncthreads();
    for (int j = threadIdx.x; j < N_REL; j += blockDim.x) {
        int v = relh[j];
        if (v) atomicAdd(&g_relcnt[j], v);
    }
}

// ---------------- BN0 stats (count-weighted moments) -------------------------
__global__ void bn0_ent_stats_k(const float* __restrict__ ent) {
    int j = threadIdx.x & 127;
    int half = threadIdx.x >> 7;
    float s = 0.f, ss = 0.f;
    for (int e = blockIdx.x * 2 + half; e < N_ENT; e += gridDim.x * 2) {
        float w = (float)g_entcnt[e];
        float v = ent[(size_t)e * D + j];
        s  += w * v;
        ss += w * v * v;
    }
    atomicAdd(&g_sum0[j], s);
    atomicAdd(&g_sumsq0[j], ss);
}
__global__ void bn0_rel_stats_k(const float* __restrict__ rel) {
    int j = threadIdx.x;
    float ss = 0.f;
    for (int r = 0; r < N_REL; r++) {
        float w = (float)g_relcnt[r];
        float v = rel[r * D + j];
        ss += w * v * v;
    }
    g_sumsqr[j] = ss;
}
__global__ void bn0_fin_k(const float* __restrict__ g0, const float* __restrict__ b0) {
    int j = threadIdx.x;  // 0..383
    float mean, var;
    if (j < 256) {
        int jj = j & 127;
        mean = g_sum0[jj] * (1.f / M_ROWS);
        var  = g_sumsq0[jj] * (1.f / M_ROWS) - mean * mean;
    } else {
        int jj = j - 256;
        mean = 0.f;
        var  = 2.f * g_sumsqr[jj] * (1.f / M_ROWS);
    }
    float inv = rsqrtf(var + BN_EPS);
    float s = inv * g0[j];
    g_s0[j] = s;
    g_t0[j] = b0[j] - mean * s;
}

// ---------------- fold BN0 into weights --------------------------------------
__global__ void wprep_k(const float* __restrict__ aw, const float* __restrict__ ab) {
    int k = blockIdx.x;   // output col 0..127
    int j = threadIdx.x;  // 0..383
    float w  = aw[k * D3 + j];
    float sc = w * g_s0[j];
    if (j < D)          g_Wcat[j * 256 + k] = sc;
    else if (j < 256)   g_Wcat[(j - D) * 256 + D + k] = sc;
    else                g_Wr[(j - 256) * D + k] = sc;
    __shared__ float red[D3];
    red[j] = g_t0[j] * w;
    __syncthreads();
    if (j < D) red[j] += red[j + D] + red[j + 256];
    __syncthreads();
    for (int off = 64; off > 0; off >>= 1) {
        if (j < off) red[j] += red[j + off];
        __syncthreads();
    }
    if (j == 0) g_biasp[k] = ab[k] + red[0];
}

// ---------------- E = ent_embed @ Wcat via tf32 mma.sync ---------------------
// Block: 64 (M) x 128 (N) tile, K chunked by 32, 8 warps in 2x4 (warp tile 32x32)
__global__ void gemm_tf32_k(const float* __restrict__ A) {
    __shared__ float As[64][36];    // pad 4: A-frag lds conflict-free
    __shared__ float Bs[32][136];   // pad 8: B-frag lds conflict-free
    int bm = blockIdx.x * 64, bn = blockIdx.y * 128;
    int tid = threadIdx.x;
    int lane = tid & 31, wid = tid >> 5;
    int wm = (wid >> 2) * 32;       // warp m offset (0/32)
    int wn = (wid & 3) * 32;        // warp n offset (0/32/64/96)
    int g = lane >> 2, t = lane & 3;

    float acc[2][4][4];
#pragma unroll
    for (int mi = 0; mi < 2; mi++)
#pragma unroll
        for (int ni = 0; ni < 4; ni++)
#pragma unroll
            for (int q = 0; q < 4; q++) acc[mi][ni][q] = 0.f;

    for (int k0 = 0; k0 < D; k0 += 32) {
        // A tile: 64x32 floats, 2 float4 per thread
#pragma unroll
        for (int i = 0; i < 2; i++) {
            int idx = tid + i * 256;
            int row = idx >> 3, c4 = (idx & 7) * 4;
            int grow = bm + row;
            float4 v = make_float4(0.f, 0.f, 0.f, 0.f);
            if (grow < N_ENT) v = *(const float4*)&A[(size_t)grow * D + k0 + c4];
            float* dst = &As[row][c4];
            dst[0] = __uint_as_float(f2tf(v.x));
            dst[1] = __uint_as_float(f2tf(v.y));
            dst[2] = __uint_as_float(f2tf(v.z));
            dst[3] = __uint_as_float(f2tf(v.w));
        }
        // B tile: 32x128 floats, 4 float4 per thread
#pragma unroll
        for (int i = 0; i < 4; i++) {
            int idx = tid + i * 256;
            int kk = idx >> 5, c4 = (idx & 31) * 4;
            float4 v = *(const float4*)&g_Wcat[(k0 + kk) * 256 + bn + c4];
            float* dst = &Bs[kk][c4];
            dst[0] = __uint_as_float(f2tf(v.x));
            dst[1] = __uint_as_float(f2tf(v.y));
            dst[2] = __uint_as_float(f2tf(v.z));
            dst[3] = __uint_as_float(f2tf(v.w));
        }
        __syncthreads();
#pragma unroll
        for (int k8 = 0; k8 < 32; k8 += 8) {
            uint32_t af[2][4], bf[4][2];
#pragma unroll
            for (int mi = 0; mi < 2; mi++) {
                int r0 = wm + mi * 16;
                af[mi][0] = __float_as_uint(As[r0 + g][k8 + t]);
                af[mi][1] = __float_as_uint(As[r0 + g + 8][k8 + t]);
                af[mi][2] = __float_as_uint(As[r0 + g][k8 + t + 4]);
                af[mi][3] = __float_as_uint(As[r0 + g + 8][k8 + t + 4]);
            }
#pragma unroll
            for (int ni = 0; ni < 4; ni++) {
                bf[ni][0] = __float_as_uint(Bs[k8 + t][wn + ni * 8 + g]);
                bf[ni][1] = __float_as_uint(Bs[k8 + t + 4][wn + ni * 8 + g]);
            }
#pragma unroll
            for (int mi = 0; mi < 2; mi++)
#pragma unroll
                for (int ni = 0; ni < 4; ni++)
                    mma_tf32(acc[mi][ni], af[mi], bf[ni]);
        }
        __syncthreads();
    }
    // epilogue: D rows g/g+8, cols 2t/2t+1
#pragma unroll
    for (int mi = 0; mi < 2; mi++) {
#pragma unroll
        for (int ni = 0; ni < 4; ni++) {
            int r0 = bm + wm + mi * 16 + g;
            int cc = bn + wn + ni * 8 + 2 * t;
            if (r0 < N_ENT)
                *(float2*)&g_E[(size_t)r0 * 256 + cc] =
                    make_float2(acc[mi][ni][0], acc[mi][ni][1]);
            if (r0 + 8 < N_ENT)
                *(float2*)&g_E[(size_t)(r0 + 8) * 256 + cc] =
                    make_float2(acc[mi][ni][2], acc[mi][ni][3]);
        }
    }
}

// ---------------- R = rel_embed @ Wr  (500 x 128) ---------------------------
__global__ void relgemm_k(const float* __restrict__ rel) {
    int r = blockIdx.x, k = threadIdx.x;
    __shared__ float rr[D];
    rr[k] = rel[r * D + k];
    __syncthreads();
    float acc = 0.f;
#pragma unroll 8
    for (int j = 0; j < D; j++) acc += rr[j] * g_Wr[j * D + k];
    g_R[r * D + k] = acc;
}

// ---------------- pass 1: BN1 column moments over 500k virtual rows ---------
__global__ void pass1_k(const int* __restrict__ trip) {
    int lane = threadIdx.x & 31;
    int warp = (blockIdx.x * blockDim.x + threadIdx.x) >> 5;
    int nw = (gridDim.x * blockDim.x) >> 5;
    float4 bias = ((const float4*)g_biasp)[lane];
    float sx = 0.f, sy = 0.f, sz = 0.f, sw = 0.f;
    float qx = 0.f, qy = 0.f, qz = 0.f, qw = 0.f;
    for (int i = warp; i < N_TRIP; i += nw) {
        int t0 = trip[3 * i], t1 = trip[3 * i + 1], t2 = trip[3 * i + 2];
        const float4* p0 = (const float4*)(g_E + (size_t)t0 * 256);
        const float4* p1 = (const float4*)(g_E + (size_t)t1 * 256);
        float4 a = p0[lane], dd = p0[lane + 32];
        float4 c = p1[lane], b  = p1[lane + 32];
        float4 r = ((const float4*)(g_R + (size_t)t2 * D))[lane];
        float cfx = a.x + b.x + r.x + bias.x, cbx = c.x + dd.x - r.x + bias.x;
        float cfy = a.y + b.y + r.y + bias.y, cby = c.y + dd.y - r.y + bias.y;
        float cfz = a.z + b.z + r.z + bias.z, cbz = c.z + dd.z - r.z + bias.z;
        float cfw = a.w + b.w + r.w + bias.w, cbw = c.w + dd.w - r.w + bias.w;
        sx += cfx + cbx; qx += cfx * cfx + cbx * cbx;
        sy += cfy + cby; qy += cfy * cfy + cby * cby;
        sz += cfz + cbz; qz += cfz * cfz + cbz * cbz;
        sw += cfw + cbw; qw += cfw * cfw + cbw * cbw;
    }
    red_add_v4(&g_sum1[lane * 4], sx, sy, sz, sw);
    red_add_v4(&g_sumsq1[lane * 4], qx, qy, qz, qw);
}

__global__ void bn1_fin_k(const float* __restrict__ g1, const float* __restrict__ b1,
                          const float* __restrict__ a2w, const float* __restrict__ a2b) {
    int k = threadIdx.x;  // 0..127
    float mean = g_sum1[k] * (1.f / M_ROWS);
    float var  = g_sumsq1[k] * (1.f / M_ROWS) - mean * mean;
    float inv  = rsqrtf(var + BN_EPS);
    float s = inv * g1[k];
    float t = b1[k] - mean * s;
    g_s1[k] = s;
    g_t1c[k] = t;
    // pass2 materializes the FULL post-BN1 c, so the attention dot uses raw a2.
    g_w2[k] = a2w[k];
    if (k == 0) g_c2 = a2b[0];
}

// ---------------- pass 2: attention + scatter --------------------------------
__global__ void pass2_k(const int* __restrict__ trip, float* __restrict__ hs) {
    int lane = threadIdx.x & 31;
    int warp = (blockIdx.x * blockDim.x + threadIdx.x) >> 5;
    int nw = (gridDim.x * blockDim.x) >> 5;
    int rep = blockIdx.x & (NREP - 1);
    float4 bias = ((const float4*)g_biasp)[lane];
    float4 s1v  = ((const float4*)g_s1)[lane];
    float4 t1v  = ((const float4*)g_t1c)[lane];
    float4 w2v  = ((const float4*)g_w2)[lane];
    float c2 = g_c2;
    for (int i = warp; i < N_TRIP; i += nw) {
        int t0 = trip[3 * i], t1i = trip[3 * i + 1], t2 = trip[3 * i + 2];
        const float4* p0 = (const float4*)(g_E + (size_t)t0 * 256);
        const float4* p1 = (const float4*)(g_E + (size_t)t1i * 256);
        float4 a = p0[lane], dd = p0[lane + 32];
        float4 c = p1[lane], b  = p1[lane + 32];
        float4 r = ((const float4*)(g_R + (size_t)t2 * D))[lane];
        float cfx = (a.x + b.x + r.x + bias.x) * s1v.x + t1v.x;
        float cfy = (a.y + b.y + r.y + bias.y) * s1v.y + t1v.y;
        float cfz = (a.z + b.z + r.z + bias.z) * s1v.z + t1v.z;
        float cfw = (a.w + b.w + r.w + bias.w) * s1v.w + t1v.w;
        float cbx = (c.x + dd.x - r.x + bias.x) * s1v.x + t1v.x;
        float cby = (c.y + dd.y - r.y + bias.y) * s1v.y + t1v.y;
        float cbz = (c.z + dd.z - r.z + bias.z) * s1v.z + t1v.z;
        float cbw = (c.w + dd.w - r.w + bias.w) * s1v.w + t1v.w;
        float df = cfx * w2v.x + cfy * w2v.y + cfz * w2v.z + cfw * w2v.w;
        float db = cbx * w2v.x + cby * w2v.y + cbz * w2v.z + cbw * w2v.w;
#pragma unroll
        for (int off = 16; off > 0; off >>= 1) {
            df += __shfl_xor_sync(0xFFFFFFFFu, df, off);
            db += __shfl_xor_sync(0xFFFFFFFFu, db, off);
        }
        df += c2; db += c2;
        float bf = (df >= 0.f) ? -df : -SLOPE * df;
        float bb = (db >= 0.f) ? -db : -SLOPE * db;
        float ef = expf(bf);
        float eb = expf(bb);
        red_add_v4(hs + (size_t)t0 * D + lane * 4, cfx * ef, cfy * ef, cfz * ef, cfw * ef);
        red_add_v4(hs + (size_t)t1i * D + lane * 4, cbx * eb, cby * eb, cbz * eb, cbw * eb);
        red_add_v4(g_relbuf + ((size_t)rep * N_REL + t2) * D + lane * 4,
                   cfx * ef, cfy * ef, cfz * ef, cfw * ef);
        if (lane == 0) {
            atomicAdd(&g_ebs[t0], ef);
            atomicAdd(&g_ebs[t1i], eb);
        }
    }
}

// ---------------- finalize ----------------------------------------------------
__global__ void ent_final_k(float* __restrict__ out) {
    int i = blockIdx.x * blockDim.x + threadIdx.x;
    if (i < N_ENT * D) {
        float denom = g_ebs[i >> 7];
        if (denom == 0.f) denom = 1e-12f;
        out[i] = out[i] / denom;
    }
}
__global__ void rel_final_k(float* __restrict__ out) {
    int i = blockIdx.x * blockDim.x + threadIdx.x;
    if (i < N_REL * D) {
        float s = 0.f;
#pragma unroll
        for (int rp = 0; rp < NREP; rp++) s += g_relbuf[(size_t)rp * N_REL * D + i];
        float cnt = (float)g_relcnt[i >> 7];
        out[(size_t)N_ENT * D + i] = s / fmaxf(cnt, 1.f);
    }
}

// ---------------- launch ------------------------------------------------------
extern "C" void kernel_launch(void* const* d_in, const int* in_sizes, int n_in,
                              void* d_out, int out_size) {
    const int*   trip = (const int*)d_in[0];
    const float* ent  = (const float*)d_in[1];
    const float* rel  = (const float*)d_in[2];
    const float* aw   = (const float*)d_in[3];
    const float* ab   = (const float*)d_in[4];
    const float* a2w  = (const float*)d_in[5];
    const float* a2b  = (const float*)d_in[6];
    const float* bn0g = (const float*)d_in[7];
    const float* bn0b = (const float*)d_in[8];
    const float* bn1g = (const float*)d_in[9];
    const float* bn1b = (const float*)d_in[10];
    float* out = (float*)d_out;

    zero_out_k<<<4096, 256>>>((float4*)out, (N_ENT * D + N_REL * D) / 4);
    zero_misc_k<<<(N_ENT + 255) / 256, 256>>>();
    zero_relbuf_k<<<2048, 256>>>();
    count_k<<<148, 256>>>(trip);
    bn0_ent_stats_k<<<592, 256>>>(ent);
    bn0_rel_stats_k<<<1, 128>>>(rel);
    bn0_fin_k<<<1, 384>>>(bn0g, bn0b);
    wprep_k<<<128, 384>>>(aw, ab);
    gemm_tf32_k<<<dim3((N_ENT + 63) / 64, 2), 256>>>(ent);
    relgemm_k<<<N_REL, 128>>>(rel);
    pass1_k<<<1184, 256>>>(trip);
    bn1_fin_k<<<1, 128>>>(bn1g, bn1b, a2w, a2b);
    pass2_k<<<1184, 256>>>(trip, out);
    ent_final_k<<<(N_ENT * D + 255) / 256, 256>>>(out);
    rel_final_k<<<(N_REL * D + 255) / 256, 256>>>(out);
}